// round 3
// baseline (speedup 1.0000x reference)
#include <cuda_runtime.h>
#include <math.h>

#define Bk 8
#define Sk 128
#define Dk 300
#define Ek 50
#define DEPk 50

// Scratch (no allocations allowed)
__device__ float g_Abar[Bk * Sk * Sk];      // (B,S,S)
__device__ float g_Ax[Bk * Sk * Dk];        // (B,S,D)
__device__ float g_Wt[Dk * Dk];             // Wt[d*D+i] = W[i*D+d]
__device__ float g_W1t[Dk * 2 * DEPk];      // W1t[d*100+j]: j<50 -> W1[j][d], else W1[j-50][300+d]
__device__ float g_pa[Bk * Sk * DEPk];
__device__ float g_pb[Bk * Sk * DEPk];

// ---------------------------------------------------------------------------
// K1: Abar[b,s,t] = (1/E) * ( sum_e wps[b,s,t,e] + sum_e sl[b,e,s,t] )
// ---------------------------------------------------------------------------
__global__ __launch_bounds__(128) void k_abar(const float* __restrict__ wps,
                                              const float* __restrict__ sl) {
    const int t = threadIdx.x;
    const int s = blockIdx.x;
    const int b = blockIdx.y;

    const float2* w2 = reinterpret_cast<const float2*>(
        wps + ((size_t)((b * Sk + s) * Sk) + t) * Ek);
    float s1 = 0.f;
#pragma unroll
    for (int e = 0; e < Ek / 2; ++e) {
        float2 v = w2[e];
        s1 += v.x + v.y;
    }

    const float* sp = sl + (size_t)b * Ek * Sk * Sk + s * Sk + t;
    float s2 = 0.f;
#pragma unroll
    for (int e = 0; e < Ek; ++e) s2 += sp[(size_t)e * Sk * Sk];

    g_Abar[(b * Sk + s) * Sk + t] = (s1 + s2) * (1.0f / Ek);
}

// ---------------------------------------------------------------------------
// K2: Ax[b,s,d] = sum_t Abar[b,s,t] * x[b,t,d]   (x staged through smem)
// grid (S/8, B), 128 threads; thread owns d = tid, tid+128, tid+256
// ---------------------------------------------------------------------------
#define ST2 8
#define TC2 32
__global__ __launch_bounds__(128) void k_ax(const float* __restrict__ x) {
    __shared__ float Ab[ST2][Sk];        // 4 KB
    __shared__ float xs[TC2][Dk];        // 38.4 KB
    const int tid = threadIdx.x;
    const int s0 = blockIdx.x * ST2;
    const int b = blockIdx.y;

#pragma unroll
    for (int r = 0; r < ST2; ++r)
        Ab[r][tid] = g_Abar[(b * Sk + s0 + r) * Sk + tid];

    const int d0 = tid, d1 = tid + 128, d2 = tid + 256;
    const bool v2 = (d2 < Dk);

    float acc[ST2][3];
#pragma unroll
    for (int r = 0; r < ST2; ++r)
        acc[r][0] = acc[r][1] = acc[r][2] = 0.f;

    for (int t0 = 0; t0 < Sk; t0 += TC2) {
        __syncthreads();
#pragma unroll 4
        for (int r2 = 0; r2 < TC2; ++r2) {
            const float* xr = x + (size_t)(b * Sk + t0 + r2) * Dk;
            for (int c = tid; c < Dk; c += 128) xs[r2][c] = xr[c];
        }
        __syncthreads();

#pragma unroll
        for (int tt = 0; tt < TC2; tt += 4) {
            float xa0 = xs[tt + 0][d0], xb0 = xs[tt + 0][d1];
            float xa1 = xs[tt + 1][d0], xb1 = xs[tt + 1][d1];
            float xa2 = xs[tt + 2][d0], xb2 = xs[tt + 2][d1];
            float xa3 = xs[tt + 3][d0], xb3 = xs[tt + 3][d1];
            float xc0 = v2 ? xs[tt + 0][d2] : 0.f;
            float xc1 = v2 ? xs[tt + 1][d2] : 0.f;
            float xc2 = v2 ? xs[tt + 2][d2] : 0.f;
            float xc3 = v2 ? xs[tt + 3][d2] : 0.f;
#pragma unroll
            for (int r = 0; r < ST2; ++r) {
                float4 a = *reinterpret_cast<const float4*>(&Ab[r][t0 + tt]);
                acc[r][0] = fmaf(a.x, xa0, acc[r][0]);
                acc[r][0] = fmaf(a.y, xa1, acc[r][0]);
                acc[r][0] = fmaf(a.z, xa2, acc[r][0]);
                acc[r][0] = fmaf(a.w, xa3, acc[r][0]);
                acc[r][1] = fmaf(a.x, xb0, acc[r][1]);
                acc[r][1] = fmaf(a.y, xb1, acc[r][1]);
                acc[r][1] = fmaf(a.z, xb2, acc[r][1]);
                acc[r][1] = fmaf(a.w, xb3, acc[r][1]);
                acc[r][2] = fmaf(a.x, xc0, acc[r][2]);
                acc[r][2] = fmaf(a.y, xc1, acc[r][2]);
                acc[r][2] = fmaf(a.z, xc2, acc[r][2]);
                acc[r][2] = fmaf(a.w, xc3, acc[r][2]);
            }
        }
    }
#pragma unroll
    for (int r = 0; r < ST2; ++r) {
        float* o = g_Ax + (size_t)(b * Sk + s0 + r) * Dk;
        o[d0] = acc[r][0];
        o[d1] = acc[r][1];
        if (v2) o[d2] = acc[r][2];
    }
}

// ---------------------------------------------------------------------------
// Prep A: tiled transpose of W -> g_Wt
// ---------------------------------------------------------------------------
__global__ void k_wt(const float* __restrict__ W) {
    __shared__ float tile[32][33];
    const int x0 = blockIdx.x * 32, y0 = blockIdx.y * 32;
    const int tx = threadIdx.x, ty = threadIdx.y;  // 32x8
#pragma unroll
    for (int j = 0; j < 32; j += 8) {
        int i = y0 + ty + j, d = x0 + tx;
        if (i < Dk && d < Dk) tile[ty + j][tx] = W[i * Dk + d];
    }
    __syncthreads();
#pragma unroll
    for (int j = 0; j < 32; j += 8) {
        int d = x0 + ty + j, i = y0 + tx;
        if (d < Dk && i < Dk) g_Wt[d * Dk + i] = tile[tx][ty + j];
    }
}

// ---------------------------------------------------------------------------
// Prep B: W1t[d*100+j] (coalesced writes)
// ---------------------------------------------------------------------------
__global__ __launch_bounds__(128) void k_w1t(const float* __restrict__ W1) {
    const int d = blockIdx.x;
    const int j = threadIdx.x;
    if (j < 2 * DEPk) {
        float v = (j < DEPk) ? W1[(size_t)j * (2 * Dk) + d]
                             : W1[(size_t)(j - DEPk) * (2 * Dk) + Dk + d];
        g_W1t[d * (2 * DEPk) + j] = v;
    }
}

// ---------------------------------------------------------------------------
// K3: g = Ax@W^T + b -> LayerNorm(ddof=1) -> ReLU -> node; then pa/pb epilogue.
// grid (S/8, B), 320 threads. Wt and W1t staged through smem chunks.
// ---------------------------------------------------------------------------
#define ST3 8
#define KC 20     // k-chunk for Wt (multiple of 4): 15 chunks of 20x300
#define DC 60     // d-chunk for W1t (multiple of 4): 5 chunks of 60x100
__global__ __launch_bounds__(320) void k_fused(const float* __restrict__ Wb,
                                               const float* __restrict__ lna,
                                               const float* __restrict__ lnb,
                                               float* __restrict__ node) {
    __shared__ float Axs[ST3][Dk];       // 9.6 KB: Ax rows, later g, later node
    __shared__ float Ws[KC * Dk];        // 24 KB: Wt chunks, reused for W1t chunks
    __shared__ float mean_s[ST3], inv_s[ST3];

    const int tid = threadIdx.x;
    const int s0 = blockIdx.x * ST3;
    const int b = blockIdx.y;

    for (int idx = tid; idx < ST3 * Dk; idx += 320) {
        int r = idx / Dk, c = idx - r * Dk;
        Axs[r][c] = g_Ax[(size_t)(b * Sk + s0 + r) * Dk + c];
    }

    const int i = tid;
    float acc[ST3];
#pragma unroll
    for (int r = 0; r < ST3; ++r) acc[r] = 0.f;

    for (int ch = 0; ch < Dk / KC; ++ch) {
        __syncthreads();
        const float* wsrc = g_Wt + (size_t)ch * KC * Dk;
        for (int idx = tid; idx < KC * Dk; idx += 320) Ws[idx] = wsrc[idx];
        __syncthreads();

        if (i < Dk) {
            const int k0 = ch * KC;
#pragma unroll
            for (int kk = 0; kk < KC; kk += 4) {
                float w0 = Ws[(kk + 0) * Dk + i];
                float w1 = Ws[(kk + 1) * Dk + i];
                float w2 = Ws[(kk + 2) * Dk + i];
                float w3 = Ws[(kk + 3) * Dk + i];
#pragma unroll
                for (int r = 0; r < ST3; ++r) {
                    float4 a = *reinterpret_cast<const float4*>(&Axs[r][k0 + kk]);
                    acc[r] = fmaf(a.x, w0, acc[r]);
                    acc[r] = fmaf(a.y, w1, acc[r]);
                    acc[r] = fmaf(a.z, w2, acc[r]);
                    acc[r] = fmaf(a.w, w3, acc[r]);
                }
            }
        }
    }
    __syncthreads();

    // g -> Axs (reuse)
    if (i < Dk) {
        float bias = Wb[i];
#pragma unroll
        for (int r = 0; r < ST3; ++r) Axs[r][i] = acc[r] + bias;
    }
    __syncthreads();

    // per-row LN stats (warp w -> row w)
    const int w = tid >> 5, lane = tid & 31;
    if (w < ST3) {
        float sum = 0.f, sq = 0.f;
        for (int c = lane; c < Dk; c += 32) {
            float v = Axs[w][c];
            sum += v;
            sq = fmaf(v, v, sq);
        }
#pragma unroll
        for (int o = 16; o > 0; o >>= 1) {
            sum += __shfl_xor_sync(0xffffffffu, sum, o);
            sq += __shfl_xor_sync(0xffffffffu, sq, o);
        }
        if (lane == 0) {
            float m = sum * (1.0f / Dk);
            float var = (sq - (float)Dk * m * m) * (1.0f / (Dk - 1));
            float sd = sqrtf(fmaxf(var, 0.f));
            mean_s[w] = m;
            inv_s[w] = 1.0f / (sd + 1e-6f);
        }
    }
    __syncthreads();

    // normalize + relu -> node (global) and Axs (for pa/pb)
    if (i < Dk) {
        float a = lna[i], bb = lnb[i];
#pragma unroll
        for (int r = 0; r < ST3; ++r) {
            float v = a * (Axs[r][i] - mean_s[r]) * inv_s[r] + bb;
            v = fmaxf(v, 0.f);
            Axs[r][i] = v;
            node[(size_t)(b * Sk + s0 + r) * Dk + i] = v;
        }
    }

    // pa/pb epilogue: thread j<100 owns output col j across the 8 rows
    float pacc[ST3];
#pragma unroll
    for (int r = 0; r < ST3; ++r) pacc[r] = 0.f;

    for (int ch = 0; ch < Dk / DC; ++ch) {
        __syncthreads();
        const float* wsrc = g_W1t + (size_t)ch * DC * (2 * DEPk);
        for (int idx = tid; idx < DC * 2 * DEPk; idx += 320) Ws[idx] = wsrc[idx];
        __syncthreads();

        if (tid < 2 * DEPk) {
            const int d0c = ch * DC;
#pragma unroll
            for (int dd = 0; dd < DC; dd += 4) {
                float w0 = Ws[(dd + 0) * (2 * DEPk) + tid];
                float w1 = Ws[(dd + 1) * (2 * DEPk) + tid];
                float w2 = Ws[(dd + 2) * (2 * DEPk) + tid];
                float w3 = Ws[(dd + 3) * (2 * DEPk) + tid];
#pragma unroll
                for (int r = 0; r < ST3; ++r) {
                    float4 a = *reinterpret_cast<const float4*>(&Axs[r][d0c + dd]);
                    pacc[r] = fmaf(a.x, w0, pacc[r]);
                    pacc[r] = fmaf(a.y, w1, pacc[r]);
                    pacc[r] = fmaf(a.z, w2, pacc[r]);
                    pacc[r] = fmaf(a.w, w3, pacc[r]);
                }
            }
        }
    }

    if (tid < 2 * DEPk) {
        const bool is_a = (tid < DEPk);
        const int k = is_a ? tid : tid - DEPk;
        float* o = is_a ? g_pa : g_pb;
#pragma unroll
        for (int r = 0; r < ST3; ++r)
            o[(size_t)(b * Sk + s0 + r) * DEPk + k] = pacc[r];
    }
}

// ---------------------------------------------------------------------------
// K5: edge[b,i,j,k] = pa[b,j,k] + pb[b,i,k] + W1_b[k]
// ---------------------------------------------------------------------------
__global__ __launch_bounds__(256) void k_edge(const float* __restrict__ W1b,
                                              float* __restrict__ edge) {
    __shared__ float pbb[DEPk];
    const int tid = threadIdx.x;
    const int i = blockIdx.x;
    const int b = blockIdx.y;

    if (tid < DEPk)
        pbb[tid] = g_pb[(size_t)(b * Sk + i) * DEPk + tid] + W1b[tid];
    __syncthreads();

    const float2* par = reinterpret_cast<const float2*>(g_pa + (size_t)b * Sk * DEPk);
    float2* er = reinterpret_cast<float2*>(edge + (size_t)(b * Sk + i) * Sk * DEPk);

    for (int idx = tid; idx < (Sk * DEPk) / 2; idx += 256) {
        int k = (2 * idx) % DEPk;  // DEPk even -> pair stays in one row
        float2 p = par[idx];
        p.x += pbb[k];
        p.y += pbb[k + 1];
        er[idx] = p;
    }
}

// ---------------------------------------------------------------------------
extern "C" void kernel_launch(void* const* d_in, const int* in_sizes, int n_in,
                              void* d_out, int out_size) {
    const float* wps = (const float*)d_in[0];   // (B,S,S,E)
    const float* x   = (const float*)d_in[2];   // (B,S,D)
    const float* sl  = (const float*)d_in[3];   // (B,E,S,S)
    const float* Ww  = (const float*)d_in[4];   // (D,D)
    const float* Wb  = (const float*)d_in[5];   // (D,)
    const float* lna = (const float*)d_in[6];   // (D,)
    const float* lnb = (const float*)d_in[7];   // (D,)
    const float* W1  = (const float*)d_in[8];   // (DEP, 2D)
    const float* W1b = (const float*)d_in[9];   // (DEP,)

    float* out = (float*)d_out;
    float* node = out;                          // (B,S,D)
    float* edge = out + (size_t)Bk * Sk * Dk;   // (B,S,S,DEP)

    k_abar<<<dim3(Sk, Bk), 128>>>(wps, sl);
    k_wt<<<dim3(10, 10), dim3(32, 8)>>>(Ww);
    k_w1t<<<dim3(Dk), 128>>>(W1);
    k_ax<<<dim3(Sk / ST2, Bk), 128>>>(x);
    k_fused<<<dim3(Sk / ST3, Bk), 320>>>(Wb, lna, lnb, node);
    k_edge<<<dim3(Sk, Bk), 256>>>(W1b, edge);
}

// round 5
// speedup vs baseline: 1.9058x; 1.9058x over previous
#include <cuda_runtime.h>
#include <math.h>

#define Bk 8
#define Sk 128
#define Dk 300
#define Ek 50
#define DEPk 50

// Scratch (no allocations allowed)
__device__ float g_Abar[Bk * Sk * Sk];      // (B,S,S)
__device__ float g_Ax[Bk * Sk * Dk];        // (B,S,D)
__device__ float g_Wt[Dk * Dk];             // Wt[d*D+i] = W[i*D+d]
__device__ float g_W1t[Dk * 2 * DEPk];      // W1t[d*100+j]
__device__ float g_pa[Bk * Sk * DEPk];
__device__ float g_pb[Bk * Sk * DEPk];

// ---------------------------------------------------------------------------
// K1: Abar[b,s,t] = (1/E) * ( sum_e wps[b,s,t,e] + sum_e sl[b,e,s,t] )
// ---------------------------------------------------------------------------
__global__ __launch_bounds__(128) void k_abar(const float* __restrict__ wps,
                                              const float* __restrict__ sl) {
    const int t = threadIdx.x;
    const int s = blockIdx.x;
    const int b = blockIdx.y;

    const float2* w2 = reinterpret_cast<const float2*>(
        wps + ((size_t)((b * Sk + s) * Sk) + t) * Ek);
    float s1 = 0.f;
#pragma unroll
    for (int e = 0; e < Ek / 2; ++e) {
        float2 v = w2[e];
        s1 += v.x + v.y;
    }

    const float* sp = sl + (size_t)b * Ek * Sk * Sk + s * Sk + t;
    float s2 = 0.f;
#pragma unroll
    for (int e = 0; e < Ek; ++e) s2 += sp[(size_t)e * Sk * Sk];

    g_Abar[(b * Sk + s) * Sk + t] = (s1 + s2) * (1.0f / Ek);
}

// ---------------------------------------------------------------------------
// K2: Ax[b,s,d] = sum_t Abar[b,s,t] * x[b,t,d]
// grid (32, 8) = 256 blocks, 320 threads. Thread owns column d for 4 s-rows.
// x read straight from global (L2-resident), coalesced across lanes.
// ---------------------------------------------------------------------------
#define ST2 4
__global__ __launch_bounds__(320) void k_ax(const float* __restrict__ x) {
    __shared__ float Ab[ST2][Sk];        // 2 KB
    const int tid = threadIdx.x;
    const int s0 = blockIdx.x * ST2;
    const int b = blockIdx.y;

    for (int idx = tid; idx < ST2 * Sk; idx += 320)
        Ab[idx >> 7][idx & 127] = g_Abar[(size_t)(b * Sk + s0) * Sk + idx];
    __syncthreads();

    const int d = tid;
    if (d >= Dk) return;

    const float* xp = x + (size_t)b * Sk * Dk + d;
    float a0 = 0.f, a1 = 0.f, a2 = 0.f, a3 = 0.f;
#pragma unroll 8
    for (int t = 0; t < Sk; ++t) {
        float xv = xp[(size_t)t * Dk];
        a0 = fmaf(Ab[0][t], xv, a0);
        a1 = fmaf(Ab[1][t], xv, a1);
        a2 = fmaf(Ab[2][t], xv, a2);
        a3 = fmaf(Ab[3][t], xv, a3);
    }
    float* o = g_Ax + (size_t)(b * Sk + s0) * Dk + d;
    o[0 * Dk] = a0;
    o[1 * Dk] = a1;
    o[2 * Dk] = a2;
    o[3 * Dk] = a3;
}

// ---------------------------------------------------------------------------
// Prep A: tiled transpose of W -> g_Wt
// ---------------------------------------------------------------------------
__global__ void k_wt(const float* __restrict__ W) {
    __shared__ float tile[32][33];
    const int x0 = blockIdx.x * 32, y0 = blockIdx.y * 32;
    const int tx = threadIdx.x, ty = threadIdx.y;  // 32x8
#pragma unroll
    for (int j = 0; j < 32; j += 8) {
        int i = y0 + ty + j, d = x0 + tx;
        if (i < Dk && d < Dk) tile[ty + j][tx] = W[i * Dk + d];
    }
    __syncthreads();
#pragma unroll
    for (int j = 0; j < 32; j += 8) {
        int d = x0 + ty + j, i = y0 + tx;
        if (d < Dk && i < Dk) g_Wt[d * Dk + i] = tile[tx][ty + j];
    }
}

// ---------------------------------------------------------------------------
// Prep B: W1t[d*100+j] (coalesced writes)
// ---------------------------------------------------------------------------
__global__ __launch_bounds__(128) void k_w1t(const float* __restrict__ W1) {
    const int d = blockIdx.x;
    const int j = threadIdx.x;
    if (j < 2 * DEPk) {
        float v = (j < DEPk) ? W1[(size_t)j * (2 * Dk) + d]
                             : W1[(size_t)(j - DEPk) * (2 * Dk) + Dk + d];
        g_W1t[d * (2 * DEPk) + j] = v;
    }
}

// ---------------------------------------------------------------------------
// K3: g = Ax@W^T + b -> LayerNorm(ddof=1) -> ReLU -> node; then pa/pb epilogue.
// grid (S/8, B), 320 threads. Wt and W1t staged through smem chunks.
// ---------------------------------------------------------------------------
#define ST3 8
#define KC 20
#define DC 60
__global__ __launch_bounds__(320) void k_fused(const float* __restrict__ Wb,
                                               const float* __restrict__ lna,
                                               const float* __restrict__ lnb,
                                               float* __restrict__ node) {
    __shared__ float Axs[ST3][Dk];       // 9.6 KB
    __shared__ float Ws[KC * Dk];        // 24 KB
    __shared__ float mean_s[ST3], inv_s[ST3];

    const int tid = threadIdx.x;
    const int s0 = blockIdx.x * ST3;
    const int b = blockIdx.y;

    for (int idx = tid; idx < ST3 * Dk; idx += 320) {
        int r = idx / Dk, c = idx - r * Dk;
        Axs[r][c] = g_Ax[(size_t)(b * Sk + s0 + r) * Dk + c];
    }

    const int i = tid;
    float acc[ST3];
#pragma unroll
    for (int r = 0; r < ST3; ++r) acc[r] = 0.f;

    for (int ch = 0; ch < Dk / KC; ++ch) {
        __syncthreads();
        const float* wsrc = g_Wt + (size_t)ch * KC * Dk;
        for (int idx = tid; idx < KC * Dk; idx += 320) Ws[idx] = wsrc[idx];
        __syncthreads();

        if (i < Dk) {
            const int k0 = ch * KC;
#pragma unroll
            for (int kk = 0; kk < KC; kk += 4) {
                float w0 = Ws[(kk + 0) * Dk + i];
                float w1 = Ws[(kk + 1) * Dk + i];
                float w2 = Ws[(kk + 2) * Dk + i];
                float w3 = Ws[(kk + 3) * Dk + i];
#pragma unroll
                for (int r = 0; r < ST3; ++r) {
                    float4 a = *reinterpret_cast<const float4*>(&Axs[r][k0 + kk]);
                    acc[r] = fmaf(a.x, w0, acc[r]);
                    acc[r] = fmaf(a.y, w1, acc[r]);
                    acc[r] = fmaf(a.z, w2, acc[r]);
                    acc[r] = fmaf(a.w, w3, acc[r]);
                }
            }
        }
    }
    __syncthreads();

    if (i < Dk) {
        float bias = Wb[i];
#pragma unroll
        for (int r = 0; r < ST3; ++r) Axs[r][i] = acc[r] + bias;
    }
    __syncthreads();

    const int w = tid >> 5, lane = tid & 31;
    if (w < ST3) {
        float sum = 0.f, sq = 0.f;
        for (int c = lane; c < Dk; c += 32) {
            float v = Axs[w][c];
            sum += v;
            sq = fmaf(v, v, sq);
        }
#pragma unroll
        for (int o = 16; o > 0; o >>= 1) {
            sum += __shfl_xor_sync(0xffffffffu, sum, o);
            sq += __shfl_xor_sync(0xffffffffu, sq, o);
        }
        if (lane == 0) {
            float m = sum * (1.0f / Dk);
            float var = (sq - (float)Dk * m * m) * (1.0f / (Dk - 1));
            float sd = sqrtf(fmaxf(var, 0.f));
            mean_s[w] = m;
            inv_s[w] = 1.0f / (sd + 1e-6f);
        }
    }
    __syncthreads();

    if (i < Dk) {
        float a = lna[i], bb = lnb[i];
#pragma unroll
        for (int r = 0; r < ST3; ++r) {
            float v = a * (Axs[r][i] - mean_s[r]) * inv_s[r] + bb;
            v = fmaxf(v, 0.f);
            Axs[r][i] = v;
            node[(size_t)(b * Sk + s0 + r) * Dk + i] = v;
        }
    }

    float pacc[ST3];
#pragma unroll
    for (int r = 0; r < ST3; ++r) pacc[r] = 0.f;

    for (int ch = 0; ch < Dk / DC; ++ch) {
        __syncthreads();
        const float* wsrc = g_W1t + (size_t)ch * DC * (2 * DEPk);
        for (int idx = tid; idx < DC * 2 * DEPk; idx += 320) Ws[idx] = wsrc[idx];
        __syncthreads();

        if (tid < 2 * DEPk) {
            const int d0c = ch * DC;
#pragma unroll
            for (int dd = 0; dd < DC; dd += 4) {
                float w0 = Ws[(dd + 0) * (2 * DEPk) + tid];
                float w1 = Ws[(dd + 1) * (2 * DEPk) + tid];
                float w2 = Ws[(dd + 2) * (2 * DEPk) + tid];
                float w3 = Ws[(dd + 3) * (2 * DEPk) + tid];
#pragma unroll
                for (int r = 0; r < ST3; ++r) {
                    float4 a = *reinterpret_cast<const float4*>(&Axs[r][d0c + dd]);
                    pacc[r] = fmaf(a.x, w0, pacc[r]);
                    pacc[r] = fmaf(a.y, w1, pacc[r]);
                    pacc[r] = fmaf(a.z, w2, pacc[r]);
                    pacc[r] = fmaf(a.w, w3, pacc[r]);
                }
            }
        }
    }

    if (tid < 2 * DEPk) {
        const bool is_a = (tid < DEPk);
        const int k = is_a ? tid : tid - DEPk;
        float* o = is_a ? g_pa : g_pb;
#pragma unroll
        for (int r = 0; r < ST3; ++r)
            o[(size_t)(b * Sk + s0 + r) * DEPk + k] = pacc[r];
    }
}

// ---------------------------------------------------------------------------
// K5: edge[b,i,j,k] = pa[b,j,k] + pb[b,i,k] + W1_b[k]
// ---------------------------------------------------------------------------
__global__ __launch_bounds__(256) void k_edge(const float* __restrict__ W1b,
                                              float* __restrict__ edge) {
    __shared__ float pbb[DEPk];
    const int tid = threadIdx.x;
    const int i = blockIdx.x;
    const int b = blockIdx.y;

    if (tid < DEPk)
        pbb[tid] = g_pb[(size_t)(b * Sk + i) * DEPk + tid] + W1b[tid];
    __syncthreads();

    const float2* par = reinterpret_cast<const float2*>(g_pa + (size_t)b * Sk * DEPk);
    float2* er = reinterpret_cast<float2*>(edge + (size_t)(b * Sk + i) * Sk * DEPk);

    for (int idx = tid; idx < (Sk * DEPk) / 2; idx += 256) {
        int k = (2 * idx) % DEPk;
        float2 p = par[idx];
        p.x += pbb[k];
        p.y += pbb[k + 1];
        er[idx] = p;
    }
}

// ---------------------------------------------------------------------------
extern "C" void kernel_launch(void* const* d_in, const int* in_sizes, int n_in,
                              void* d_out, int out_size) {
    const float* wps = (const float*)d_in[0];   // (B,S,S,E)
    const float* x   = (const float*)d_in[2];   // (B,S,D)
    const float* sl  = (const float*)d_in[3];   // (B,E,S,S)
    const float* Ww  = (const float*)d_in[4];   // (D,D)
    const float* Wb  = (const float*)d_in[5];   // (D,)
    const float* lna = (const float*)d_in[6];   // (D,)
    const float* lnb = (const float*)d_in[7];   // (D,)
    const float* W1  = (const float*)d_in[8];   // (DEP, 2D)
    const float* W1b = (const float*)d_in[9];   // (DEP,)

    float* out = (float*)d_out;
    float* node = out;                          // (B,S,D)
    float* edge = out + (size_t)Bk * Sk * Dk;   // (B,S,S,DEP)

    k_abar<<<dim3(Sk, Bk), 128>>>(wps, sl);
    k_wt<<<dim3(10, 10), dim3(32, 8)>>>(Ww);
    k_w1t<<<dim3(Dk), 128>>>(W1);
    k_ax<<<dim3(Sk / ST2, Bk), 320>>>(x);
    k_fused<<<dim3(Sk / ST3, Bk), 320>>>(Wb, lna, lnb, node);
    k_edge<<<dim3(Sk, Bk), 256>>>(W1b, edge);
}

// round 6
// speedup vs baseline: 2.4466x; 1.2838x over previous
#include <cuda_runtime.h>
#include <math.h>

#define Bk 8
#define Sk 128
#define Dk 300
#define Ek 50
#define DEPk 50
#define AXN (Bk * Sk * Dk)

// Scratch (no allocations allowed)
__device__ float g_Abar[Bk * Sk * Sk];      // (B,S,S)
__device__ float g_Ax[2 * AXN];             // two t-half partials of (B,S,D)
__device__ float g_Wt[Dk * Dk];             // Wt[d*D+i] = W[i*D+d]
__device__ float g_W1t[Dk * 2 * DEPk];      // W1t[d*100+j]
__device__ float g_pa[Bk * Sk * DEPk];
__device__ float g_pb[Bk * Sk * DEPk];

// ---------------------------------------------------------------------------
// K1: Abar[b,s,t] = (1/E) * ( sum_e wps[b,s,t,e] + sum_e sl[b,e,s,t] )
// ---------------------------------------------------------------------------
__global__ __launch_bounds__(128) void k_abar(const float* __restrict__ wps,
                                              const float* __restrict__ sl) {
    const int t = threadIdx.x;
    const int s = blockIdx.x;
    const int b = blockIdx.y;

    const float2* w2 = reinterpret_cast<const float2*>(
        wps + ((size_t)((b * Sk + s) * Sk) + t) * Ek);
    float s1 = 0.f;
#pragma unroll
    for (int e = 0; e < Ek / 2; ++e) {
        float2 v = w2[e];
        s1 += v.x + v.y;
    }

    const float* sp = sl + (size_t)b * Ek * Sk * Sk + s * Sk + t;
    float s2 = 0.f;
#pragma unroll
    for (int e = 0; e < Ek; ++e) s2 += sp[(size_t)e * Sk * Sk];

    g_Abar[(b * Sk + s) * Sk + t] = (s1 + s2) * (1.0f / Ek);
}

// ---------------------------------------------------------------------------
// K2: partial Ax over a t-half. grid (32, 8, 2) = 512 blocks, 320 threads.
// Thread owns column d for 4 s-rows; x loads coalesced, L2-resident.
// ---------------------------------------------------------------------------
#define ST2 4
#define TH2 64
__global__ __launch_bounds__(320) void k_ax(const float* __restrict__ x) {
    __shared__ float Ab[ST2][TH2];       // 1 KB
    const int tid = threadIdx.x;
    const int s0 = blockIdx.x * ST2;
    const int b = blockIdx.y;
    const int h = blockIdx.z;
    const int t0 = h * TH2;

    if (tid < ST2 * TH2) {
        int r = tid >> 6, t = tid & 63;
        Ab[r][t] = g_Abar[(size_t)(b * Sk + s0 + r) * Sk + t0 + t];
    }
    __syncthreads();

    const int d = tid;
    if (d >= Dk) return;

    const float* xp = x + (size_t)(b * Sk + t0) * Dk + d;
    float a0 = 0.f, a1 = 0.f, a2 = 0.f, a3 = 0.f;
#pragma unroll 16
    for (int t = 0; t < TH2; ++t) {
        float xv = xp[(size_t)t * Dk];
        a0 = fmaf(Ab[0][t], xv, a0);
        a1 = fmaf(Ab[1][t], xv, a1);
        a2 = fmaf(Ab[2][t], xv, a2);
        a3 = fmaf(Ab[3][t], xv, a3);
    }
    float* o = g_Ax + (size_t)h * AXN + (size_t)(b * Sk + s0) * Dk + d;
    o[0 * Dk] = a0;
    o[1 * Dk] = a1;
    o[2 * Dk] = a2;
    o[3 * Dk] = a3;
}

// ---------------------------------------------------------------------------
// Prep A: tiled transpose of W -> g_Wt
// ---------------------------------------------------------------------------
__global__ void k_wt(const float* __restrict__ W) {
    __shared__ float tile[32][33];
    const int x0 = blockIdx.x * 32, y0 = blockIdx.y * 32;
    const int tx = threadIdx.x, ty = threadIdx.y;  // 32x8
#pragma unroll
    for (int j = 0; j < 32; j += 8) {
        int i = y0 + ty + j, d = x0 + tx;
        if (i < Dk && d < Dk) tile[ty + j][tx] = W[i * Dk + d];
    }
    __syncthreads();
#pragma unroll
    for (int j = 0; j < 32; j += 8) {
        int d = x0 + ty + j, i = y0 + tx;
        if (d < Dk && i < Dk) g_Wt[d * Dk + i] = tile[tx][ty + j];
    }
}

// ---------------------------------------------------------------------------
// Prep B: W1t[d*100+j] (coalesced writes)
// ---------------------------------------------------------------------------
__global__ __launch_bounds__(128) void k_w1t(const float* __restrict__ W1) {
    const int d = blockIdx.x;
    const int j = threadIdx.x;
    if (j < 2 * DEPk) {
        float v = (j < DEPk) ? W1[(size_t)j * (2 * Dk) + d]
                             : W1[(size_t)(j - DEPk) * (2 * Dk) + Dk + d];
        g_W1t[d * (2 * DEPk) + j] = v;
    }
}

// ---------------------------------------------------------------------------
// K3: g = Ax@W^T + b -> LN(ddof=1) -> ReLU -> node; pa/pb epilogue.
// grid (S/8, B), 640 threads: sub = tid/320 owns rows sub*4..sub*4+3.
// ---------------------------------------------------------------------------
#define ST3 8
#define RH 4      // rows per subgroup
#define KC 20
#define DC 60
__global__ __launch_bounds__(640) void k_fused(const float* __restrict__ Wb,
                                               const float* __restrict__ lna,
                                               const float* __restrict__ lnb,
                                               float* __restrict__ node) {
    __shared__ float Axs[ST3][Dk];       // 9.6 KB
    __shared__ float Ws[KC * Dk];        // 24 KB
    __shared__ float mean_s[ST3], inv_s[ST3];

    const int tid = threadIdx.x;
    const int s0 = blockIdx.x * ST3;
    const int b = blockIdx.y;
    const int sub = tid / 320;
    const int i = tid - sub * 320;
    const int rbase = sub * RH;

    // load Ax rows = sum of the two t-half partials
    for (int idx = tid; idx < ST3 * Dk; idx += 640) {
        int r = idx / Dk, c = idx - r * Dk;
        size_t g = (size_t)(b * Sk + s0 + r) * Dk + c;
        Axs[r][c] = g_Ax[g] + g_Ax[AXN + g];
    }

    float acc[RH];
#pragma unroll
    for (int r = 0; r < RH; ++r) acc[r] = 0.f;

    for (int ch = 0; ch < Dk / KC; ++ch) {
        __syncthreads();
        const float* wsrc = g_Wt + (size_t)ch * KC * Dk;
        for (int idx = tid; idx < KC * Dk; idx += 640) Ws[idx] = wsrc[idx];
        __syncthreads();

        if (i < Dk) {
            const int k0 = ch * KC;
#pragma unroll
            for (int kk = 0; kk < KC; kk += 4) {
                float w0 = Ws[(kk + 0) * Dk + i];
                float w1 = Ws[(kk + 1) * Dk + i];
                float w2 = Ws[(kk + 2) * Dk + i];
                float w3 = Ws[(kk + 3) * Dk + i];
#pragma unroll
                for (int r = 0; r < RH; ++r) {
                    float4 a = *reinterpret_cast<const float4*>(&Axs[rbase + r][k0 + kk]);
                    acc[r] = fmaf(a.x, w0, acc[r]);
                    acc[r] = fmaf(a.y, w1, acc[r]);
                    acc[r] = fmaf(a.z, w2, acc[r]);
                    acc[r] = fmaf(a.w, w3, acc[r]);
                }
            }
        }
    }
    __syncthreads();

    if (i < Dk) {
        float bias = Wb[i];
#pragma unroll
        for (int r = 0; r < RH; ++r) Axs[rbase + r][i] = acc[r] + bias;
    }
    __syncthreads();

    // per-row LN stats: warp w (w<8) handles row w
    const int w = tid >> 5, lane = tid & 31;
    if (w < ST3) {
        float sum = 0.f, sq = 0.f;
        for (int c = lane; c < Dk; c += 32) {
            float v = Axs[w][c];
            sum += v;
            sq = fmaf(v, v, sq);
        }
#pragma unroll
        for (int o = 16; o > 0; o >>= 1) {
            sum += __shfl_xor_sync(0xffffffffu, sum, o);
            sq += __shfl_xor_sync(0xffffffffu, sq, o);
        }
        if (lane == 0) {
            float m = sum * (1.0f / Dk);
            float var = (sq - (float)Dk * m * m) * (1.0f / (Dk - 1));
            float sd = sqrtf(fmaxf(var, 0.f));
            mean_s[w] = m;
            inv_s[w] = 1.0f / (sd + 1e-6f);
        }
    }
    __syncthreads();

    if (i < Dk) {
        float a = lna[i], bb = lnb[i];
#pragma unroll
        for (int r = 0; r < RH; ++r) {
            float v = a * (Axs[rbase + r][i] - mean_s[rbase + r]) * inv_s[rbase + r] + bb;
            v = fmaxf(v, 0.f);
            Axs[rbase + r][i] = v;
            node[(size_t)(b * Sk + s0 + rbase + r) * Dk + i] = v;
        }
    }

    // pa/pb epilogue: threads i<100 per sub handle 4 rows each
    float pacc[RH];
#pragma unroll
    for (int r = 0; r < RH; ++r) pacc[r] = 0.f;

    for (int ch = 0; ch < Dk / DC; ++ch) {
        __syncthreads();
        const float* wsrc = g_W1t + (size_t)ch * DC * (2 * DEPk);
        for (int idx = tid; idx < DC * 2 * DEPk; idx += 640) Ws[idx] = wsrc[idx];
        __syncthreads();

        if (i < 2 * DEPk) {
            const int d0c = ch * DC;
#pragma unroll
            for (int dd = 0; dd < DC; dd += 4) {
                float w0 = Ws[(dd + 0) * (2 * DEPk) + i];
                float w1 = Ws[(dd + 1) * (2 * DEPk) + i];
                float w2 = Ws[(dd + 2) * (2 * DEPk) + i];
                float w3 = Ws[(dd + 3) * (2 * DEPk) + i];
#pragma unroll
                for (int r = 0; r < RH; ++r) {
                    float4 a = *reinterpret_cast<const float4*>(&Axs[rbase + r][d0c + dd]);
                    pacc[r] = fmaf(a.x, w0, pacc[r]);
                    pacc[r] = fmaf(a.y, w1, pacc[r]);
                    pacc[r] = fmaf(a.z, w2, pacc[r]);
                    pacc[r] = fmaf(a.w, w3, pacc[r]);
                }
            }
        }
    }

    if (i < 2 * DEPk) {
        const bool is_a = (i < DEPk);
        const int k = is_a ? i : i - DEPk;
        float* o = is_a ? g_pa : g_pb;
#pragma unroll
        for (int r = 0; r < RH; ++r)
            o[(size_t)(b * Sk + s0 + rbase + r) * DEPk + k] = pacc[r];
    }
}

// ---------------------------------------------------------------------------
// K5: edge[b,i,j,k] = pa[b,j,k] + pb[b,i,k] + W1_b[k]
// ---------------------------------------------------------------------------
__global__ __launch_bounds__(256) void k_edge(const float* __restrict__ W1b,
                                              float* __restrict__ edge) {
    __shared__ float pbb[DEPk];
    const int tid = threadIdx.x;
    const int i = blockIdx.x;
    const int b = blockIdx.y;

    if (tid < DEPk)
        pbb[tid] = g_pb[(size_t)(b * Sk + i) * DEPk + tid] + W1b[tid];
    __syncthreads();

    const float2* par = reinterpret_cast<const float2*>(g_pa + (size_t)b * Sk * DEPk);
    float2* er = reinterpret_cast<float2*>(edge + (size_t)(b * Sk + i) * Sk * DEPk);

    for (int idx = tid; idx < (Sk * DEPk) / 2; idx += 256) {
        int k = (2 * idx) % DEPk;
        float2 p = par[idx];
        p.x += pbb[k];
        p.y += pbb[k + 1];
        er[idx] = p;
    }
}

// ---------------------------------------------------------------------------
extern "C" void kernel_launch(void* const* d_in, const int* in_sizes, int n_in,
                              void* d_out, int out_size) {
    const float* wps = (const float*)d_in[0];   // (B,S,S,E)
    const float* x   = (const float*)d_in[2];   // (B,S,D)
    const float* sl  = (const float*)d_in[3];   // (B,E,S,S)
    const float* Ww  = (const float*)d_in[4];   // (D,D)
    const float* Wb  = (const float*)d_in[5];   // (D,)
    const float* lna = (const float*)d_in[6];   // (D,)
    const float* lnb = (const float*)d_in[7];   // (D,)
    const float* W1  = (const float*)d_in[8];   // (DEP, 2D)
    const float* W1b = (const float*)d_in[9];   // (DEP,)

    float* out = (float*)d_out;
    float* node = out;                          // (B,S,D)
    float* edge = out + (size_t)Bk * Sk * Dk;   // (B,S,S,DEP)

    k_abar<<<dim3(Sk, Bk), 128>>>(wps, sl);
    k_wt<<<dim3(10, 10), dim3(32, 8)>>>(Ww);
    k_w1t<<<dim3(Dk), 128>>>(W1);
    k_ax<<<dim3(Sk / ST2, Bk, 2), 320>>>(x);
    k_fused<<<dim3(Sk / ST3, Bk), 640>>>(Wb, lna, lnb, node);
    k_edge<<<dim3(Sk, Bk), 256>>>(W1b, edge);
}

// round 10
// speedup vs baseline: 3.0884x; 1.2623x over previous
#include <cuda_runtime.h>
#include <math.h>

#define Bk 8
#define Sk 128
#define Dk 300
#define Ek 50
#define DEPk 50
#define AXN (Bk * Sk * Dk)
#define NSPLIT 4

// Scratch (no allocations allowed)
__device__ float g_Abar[Bk * Sk * Sk];      // (B,S,S)
__device__ float g_Ax[NSPLIT * AXN];        // t-quarter partials of (B,S,D)
__device__ float g_Wt[Dk * Dk];             // Wt[d*D+i] = W[i*D+d]
__device__ float g_W1t[Dk * 2 * DEPk];      // W1t[d*100+j]
__device__ float g_pa[Bk * Sk * DEPk];
__device__ float g_pb[Bk * Sk * DEPk];

// ---------------------------------------------------------------------------
// K1: Abar[b,s,t] = (1/E) * ( sum_e wps[b,s,t,e] + sum_e sl[b,e,s,t] )
// ---------------------------------------------------------------------------
__global__ __launch_bounds__(128) void k_abar(const float* __restrict__ wps,
                                              const float* __restrict__ sl) {
    const int t = threadIdx.x;
    const int s = blockIdx.x;
    const int b = blockIdx.y;

    const float2* w2 = reinterpret_cast<const float2*>(
        wps + ((size_t)((b * Sk + s) * Sk) + t) * Ek);
    float s1 = 0.f;
#pragma unroll
    for (int e = 0; e < Ek / 2; ++e) {
        float2 v = w2[e];
        s1 += v.x + v.y;
    }

    const float* sp = sl + (size_t)b * Ek * Sk * Sk + s * Sk + t;
    float s2 = 0.f;
#pragma unroll
    for (int e = 0; e < Ek; ++e) s2 += sp[(size_t)e * Sk * Sk];

    g_Abar[(b * Sk + s) * Sk + t] = (s1 + s2) * (1.0f / Ek);
}

// ---------------------------------------------------------------------------
// K2: partial Ax over a t-quarter. grid (32, 8, 4) = 1024 blocks, 320 threads.
// ---------------------------------------------------------------------------
#define ST2 4
#define TH2 32
__global__ __launch_bounds__(320) void k_ax(const float* __restrict__ x) {
    __shared__ float Ab[ST2][TH2];
    const int tid = threadIdx.x;
    const int s0 = blockIdx.x * ST2;
    const int b = blockIdx.y;
    const int h = blockIdx.z;
    const int t0 = h * TH2;

    if (tid < ST2 * TH2) {
        int r = tid >> 5, t = tid & 31;
        Ab[r][t] = g_Abar[(size_t)(b * Sk + s0 + r) * Sk + t0 + t];
    }
    __syncthreads();

    const int d = tid;
    if (d >= Dk) return;

    const float* xp = x + (size_t)(b * Sk + t0) * Dk + d;
    float a0 = 0.f, a1 = 0.f, a2 = 0.f, a3 = 0.f;
#pragma unroll
    for (int t = 0; t < TH2; ++t) {
        float xv = xp[(size_t)t * Dk];
        a0 = fmaf(Ab[0][t], xv, a0);
        a1 = fmaf(Ab[1][t], xv, a1);
        a2 = fmaf(Ab[2][t], xv, a2);
        a3 = fmaf(Ab[3][t], xv, a3);
    }
    float* o = g_Ax + (size_t)h * AXN + (size_t)(b * Sk + s0) * Dk + d;
    o[0 * Dk] = a0;
    o[1 * Dk] = a1;
    o[2 * Dk] = a2;
    o[3 * Dk] = a3;
}

// ---------------------------------------------------------------------------
// Prep (merged): blocks 0..99 transpose W tiles; blocks 100..119 build W1t.
// 256 threads (as 32x8 logical for the transpose part).
// ---------------------------------------------------------------------------
__global__ __launch_bounds__(256) void k_prep(const float* __restrict__ W,
                                              const float* __restrict__ W1) {
    const int bid = blockIdx.x;
    const int tid = threadIdx.x;
    if (bid < 100) {
        __shared__ float tile[32][33];
        const int bx = bid % 10, by = bid / 10;
        const int x0 = bx * 32, y0 = by * 32;
        const int tx = tid & 31, ty = tid >> 5;  // 32x8
#pragma unroll
        for (int j = 0; j < 32; j += 8) {
            int i = y0 + ty + j, d = x0 + tx;
            if (i < Dk && d < Dk) tile[ty + j][tx] = W[i * Dk + d];
        }
        __syncthreads();
#pragma unroll
        for (int j = 0; j < 32; j += 8) {
            int d = x0 + ty + j, i = y0 + tx;
            if (d < Dk && i < Dk) g_Wt[d * Dk + i] = tile[tx][ty + j];
        }
    } else {
        // W1t: 20 blocks, each 15 d-values x 100 j = 1500 elems
        const int d0 = (bid - 100) * 15;
        for (int idx = tid; idx < 15 * 2 * DEPk; idx += 256) {
            int dl = idx / (2 * DEPk), j = idx % (2 * DEPk);
            int d = d0 + dl;
            float v = (j < DEPk) ? W1[(size_t)j * (2 * Dk) + d]
                                 : W1[(size_t)(j - DEPk) * (2 * Dk) + Dk + d];
            g_W1t[d * (2 * DEPk) + j] = v;
        }
    }
}

// ---------------------------------------------------------------------------
// K3: g = (sum of Ax partials)@W^T + b -> LN(ddof=1) -> ReLU -> node;
// pa/pb epilogue. grid (S/8, B), 640 threads.
// Double-buffered weight chunks, register prefetch, one sync per chunk.
// ---------------------------------------------------------------------------
#define ST3 8
#define RH 4
#define KCF 12           // 25 chunks of 12x300 = 3600 floats
#define DCF 30           // 10 chunks of 30x100 = 3000 floats
__global__ __launch_bounds__(640) void k_fused(const float* __restrict__ Wb,
                                               const float* __restrict__ lna,
                                               const float* __restrict__ lnb,
                                               float* __restrict__ node) {
    __shared__ float Axs[ST3][Dk];          // 9.6 KB
    __shared__ float Ws[2][KCF * Dk];       // 28.8 KB double buffer
    __shared__ float mean_s[ST3], inv_s[ST3];

    const int tid = threadIdx.x;
    const int s0 = blockIdx.x * ST3;
    const int b = blockIdx.y;
    const int sub = tid / 320;
    const int i = tid - sub * 320;
    const int rbase = sub * RH;

    // load Ax rows = sum of the NSPLIT t-quarter partials
    for (int idx = tid; idx < ST3 * Dk; idx += 640) {
        int r = idx / Dk, c = idx - r * Dk;
        size_t g = (size_t)(b * Sk + s0 + r) * Dk + c;
        Axs[r][c] = (g_Ax[g] + g_Ax[AXN + g]) +
                    (g_Ax[2 * AXN + g] + g_Ax[3 * AXN + g]);
    }

    // stage Wt chunk 0
    for (int idx = tid; idx < KCF * Dk; idx += 640) Ws[0][idx] = g_Wt[idx];
    __syncthreads();

    float acc[RH];
#pragma unroll
    for (int r = 0; r < RH; ++r) acc[r] = 0.f;

    int cur = 0;
    float pref[6];
    for (int ch = 0; ch < Dk / KCF; ++ch) {
        if (ch < Dk / KCF - 1) {
            const float* src = g_Wt + (size_t)(ch + 1) * KCF * Dk;
#pragma unroll
            for (int k = 0; k < 6; ++k) {
                int idx = tid + k * 640;
                pref[k] = (idx < KCF * Dk) ? src[idx] : 0.f;
            }
        }
        if (i < Dk) {
            const int k0 = ch * KCF;
#pragma unroll
            for (int kk = 0; kk < KCF; kk += 4) {
                float w0 = Ws[cur][(kk + 0) * Dk + i];
                float w1 = Ws[cur][(kk + 1) * Dk + i];
                float w2 = Ws[cur][(kk + 2) * Dk + i];
                float w3 = Ws[cur][(kk + 3) * Dk + i];
#pragma unroll
                for (int r = 0; r < RH; ++r) {
                    float4 a = *reinterpret_cast<const float4*>(&Axs[rbase + r][k0 + kk]);
                    acc[r] = fmaf(a.x, w0, acc[r]);
                    acc[r] = fmaf(a.y, w1, acc[r]);
                    acc[r] = fmaf(a.z, w2, acc[r]);
                    acc[r] = fmaf(a.w, w3, acc[r]);
                }
            }
        }
        if (ch < Dk / KCF - 1) {
#pragma unroll
            for (int k = 0; k < 6; ++k) {
                int idx = tid + k * 640;
                if (idx < KCF * Dk) Ws[cur ^ 1][idx] = pref[k];
            }
        }
        __syncthreads();
        cur ^= 1;
    }

    if (i < Dk) {
        float bias = Wb[i];
#pragma unroll
        for (int r = 0; r < RH; ++r) Axs[rbase + r][i] = acc[r] + bias;
    }
    __syncthreads();

    // per-row LN stats: warp w (w<8) handles row w
    const int w = tid >> 5, lane = tid & 31;
    if (w < ST3) {
        float sum = 0.f, sq = 0.f;
        for (int c = lane; c < Dk; c += 32) {
            float v = Axs[w][c];
            sum += v;
            sq = fmaf(v, v, sq);
        }
#pragma unroll
        for (int o = 16; o > 0; o >>= 1) {
            sum += __shfl_xor_sync(0xffffffffu, sum, o);
            sq += __shfl_xor_sync(0xffffffffu, sq, o);
        }
        if (lane == 0) {
            float m = sum * (1.0f / Dk);
            float var = (sq - (float)Dk * m * m) * (1.0f / (Dk - 1));
            float sd = sqrtf(fmaxf(var, 0.f));
            mean_s[w] = m;
            inv_s[w] = 1.0f / (sd + 1e-6f);
        }
    }
    __syncthreads();

    if (i < Dk) {
        float a = lna[i], bb = lnb[i];
#pragma unroll
        for (int r = 0; r < RH; ++r) {
            float v = a * (Axs[rbase + r][i] - mean_s[rbase + r]) * inv_s[rbase + r] + bb;
            v = fmaxf(v, 0.f);
            Axs[rbase + r][i] = v;
            node[(size_t)(b * Sk + s0 + rbase + r) * Dk + i] = v;
        }
    }
    __syncthreads();

    // pa/pb epilogue, double-buffered W1t chunks (30 x 100 each)
    for (int idx = tid; idx < DCF * 2 * DEPk; idx += 640) Ws[0][idx] = g_W1t[idx];
    __syncthreads();

    float pacc[RH];
#pragma unroll
    for (int r = 0; r < RH; ++r) pacc[r] = 0.f;

    cur = 0;
    float pref2[5];
    for (int ch = 0; ch < Dk / DCF; ++ch) {
        if (ch < Dk / DCF - 1) {
            const float* src = g_W1t + (size_t)(ch + 1) * DCF * (2 * DEPk);
#pragma unroll
            for (int k = 0; k < 5; ++k) {
                int idx = tid + k * 640;
                pref2[k] = (idx < DCF * 2 * DEPk) ? src[idx] : 0.f;
            }
        }
        if (i < 2 * DEPk) {
            const int d0c = ch * DCF;
#pragma unroll
            for (int dd = 0; dd < DCF; dd += 2) {
                float w0 = Ws[cur][(dd + 0) * (2 * DEPk) + i];
                float w1 = Ws[cur][(dd + 1) * (2 * DEPk) + i];
#pragma unroll
                for (int r = 0; r < RH; ++r) {
                    float a0 = Axs[rbase + r][d0c + dd];
                    float a1 = Axs[rbase + r][d0c + dd + 1];
                    pacc[r] = fmaf(a0, w0, pacc[r]);
                    pacc[r] = fmaf(a1, w1, pacc[r]);
                }
            }
        }
        if (ch < Dk / DCF - 1) {
#pragma unroll
            for (int k = 0; k < 5; ++k) {
                int idx = tid + k * 640;
                if (idx < DCF * 2 * DEPk) Ws[cur ^ 1][idx] = pref2[k];
            }
        }
        __syncthreads();
        cur ^= 1;
    }

    if (i < 2 * DEPk) {
        const bool is_a = (i < DEPk);
        const int k = is_a ? i : i - DEPk;
        float* o = is_a ? g_pa : g_pb;
#pragma unroll
        for (int r = 0; r < RH; ++r)
            o[(size_t)(b * Sk + s0 + rbase + r) * DEPk + k] = pacc[r];
    }
}

// ---------------------------------------------------------------------------
// K5: edge[b,i,j,k] = pa[b,j,k] + pb[b,i,k] + W1_b[k]
// ---------------------------------------------------------------------------
__global__ __launch_bounds__(256) void k_edge(const float* __restrict__ W1b,
                                              float* __restrict__ edge) {
    __shared__ float pbb[DEPk];
    const int tid = threadIdx.x;
    const int i = blockIdx.x;
    const int b = blockIdx.y;

    if (tid < DEPk)
        pbb[tid] = g_pb[(size_t)(b * Sk + i) * DEPk + tid] + W1b[tid];
    __syncthreads();

    const float2* par = reinterpret_cast<const float2*>(g_pa + (size_t)b * Sk * DEPk);
    float2* er = reinterpret_cast<float2*>(edge + (size_t)(b * Sk + i) * Sk * DEPk);

    for (int idx = tid; idx < (Sk * DEPk) / 2; idx += 256) {
        int k = (2 * idx) % DEPk;
        float2 p = par[idx];
        p.x += pbb[k];
        p.y += pbb[k + 1];
        er[idx] = p;
    }
}

// ---------------------------------------------------------------------------
extern "C" void kernel_launch(void* const* d_in, const int* in_sizes, int n_in,
                              void* d_out, int out_size) {
    const float* wps = (const float*)d_in[0];   // (B,S,S,E)
    const float* x   = (const float*)d_in[2];   // (B,S,D)
    const float* sl  = (const float*)d_in[3];   // (B,E,S,S)
    const float* Ww  = (const float*)d_in[4];   // (D,D)
    const float* Wb  = (const float*)d_in[5];   // (D,)
    const float* lna = (const float*)d_in[6];   // (D,)
    const float* lnb = (const float*)d_in[7];   // (D,)
    const float* W1  = (const float*)d_in[8];   // (DEP, 2D)
    const float* W1b = (const float*)d_in[9];   // (DEP,)

    float* out = (float*)d_out;
    float* node = out;                          // (B,S,D)
    float* edge = out + (size_t)Bk * Sk * Dk;   // (B,S,S,DEP)

    k_abar<<<dim3(Sk, Bk), 128>>>(wps, sl);
    k_prep<<<dim3(120), 256>>>(Ww, W1);
    k_ax<<<dim3(Sk / ST2, Bk, NSPLIT), 320>>>(x);
    k_fused<<<dim3(Sk / ST3, Bk), 640>>>(Wb, lna, lnb, node);
    k_edge<<<dim3(Sk, Bk), 256>>>(W1b, edge);
}